// round 16
// baseline (speedup 1.0000x reference)
#include <cuda_runtime.h>
#include <cstddef>
#include <cstdint>

// Problem constants (match reference)
#define BB 4
#define CC 256
#define HH 512
#define WW 512
#define NROIS 32
#define OUT 7
#define TS 68        // row stride in floats (16B-aligned, 17 chunks)
#define KP 8         // planes (channels) per CTA
#define HRW 10       // max rows in one output row-group (h<=63 -> <=10)

__device__ __forceinline__ void cp_async16(uint32_t smem_dst, const void* gmem_src) {
    asm volatile("cp.async.cg.shared.global [%0], [%1], 16;\n"
                 :: "r"(smem_dst), "l"(gmem_src));
}
__device__ __forceinline__ void cp_commit() {
    asm volatile("cp.async.commit_group;\n" ::: "memory");
}
template <int N>
__device__ __forceinline__ void cp_wait() {
    asm volatile("cp.async.wait_group %0;\n" :: "n"(N) : "memory");
}

// One CTA per (roi, b, c-group-of-8), 224 threads = 7 autonomous warps.
// Warp g owns output row-group g end-to-end (stage -> vertical -> bins);
// no __syncthreads anywhere. This round: parity-split vertical (all 32
// lanes) + parity-split horizontal (14 lanes) + KP=8 setup amortization.
__global__ __launch_bounds__(224)
void roi_adaptive_pool_kernel(const float* __restrict__ x,
                              const void* __restrict__ rois_raw,
                              float* __restrict__ out)
{
    int bid  = blockIdx.x;
    int roi  = bid & (NROIS - 1);     // fastest dim -> balanced waves
    int rest = bid >> 5;
    int cg   = rest & (CC / KP - 1);  // 0..31
    int b    = rest >> 5;

    // ---- inline dtype probe + box read (L2-resident after wave 1) ----
    const long long* r64 = (const long long*)rois_raw;
    const int*       r32 = (const int*)rois_raw;
    long long p0 = r64[0], p1 = r64[1], p2 = r64[2], p3 = r64[3];
    bool is64 = (p0 >= 0 && p0 <= WW) && (p1 >= 0 && p1 <= HH) &&
                (p2 > p0 && p2 <= WW) && (p3 > p1 && p3 <= HH);
    int x1, y1, x2, y2;
    if (is64) {
        const long long* r = r64 + (size_t)roi * 4;
        x1 = (int)r[0]; y1 = (int)r[1]; x2 = (int)r[2]; y2 = (int)r[3];
    } else {
        const int* r = r32 + (size_t)roi * 4;
        x1 = r[0]; y1 = r[1]; x2 = r[2]; y2 = r[3];
    }

    int w  = x2 - x1;                  // 16..63
    int h  = y2 - y1;                  // 16..63
    int xa = x1 & ~3;                  // 16B-aligned row start
    int ox = x1 - xa;                  // 0..3
    int nc = (x2 - xa + 3) >> 2;       // float4 chunks per row (4..17)

    __shared__ float tile[OUT][2][HRW * TS];   // 7 x 2 x 2720 B = 38080 B
    __shared__ float colsum[OUT][TS];          // 1904 B

    int c0 = cg * KP;
    const float* plane0 = x + ((size_t)(b * CC + c0)) * (HH * WW);

    int lane = threadIdx.x & 31;
    int g    = threadIdx.x >> 5;       // warp id = output row group 0..6

    int ghs = (g * h) / OUT;
    int ghe = ((g + 1) * h + OUT - 1) / OUT;   // <= 10 rows
    int nrows = ghe - ghs;

    // staging: laneA = chunk (0..15), half = row parity within group
    int laneA = lane & 15;
    int half  = lane >> 4;
    int ncm   = nc < 16 ? nc : 16;
    bool doA  = laneA < ncm;
    bool doX  = (nc > 16) && (laneA == 15);    // 17th chunk

    const char* gbase = (const char*)(plane0 + (size_t)(y1 + ghs + half) * WW + xa)
                        + laneA * 16;
    uint32_t sbw[2];
    sbw[0] = (uint32_t)__cvta_generic_to_shared(tile[g][0])
             + (uint32_t)(half * TS + laneA * 4) * 4u;
    sbw[1] = (uint32_t)__cvta_generic_to_shared(tile[g][1])
             + (uint32_t)(half * TS + laneA * 4) * 4u;

    // horizontal geometry: 2 lanes per bin (parity columns), bins clamped
    int bj = lane >> 1;
    if (bj > 6) bj = 6;                // lanes 14..31 shadow bin 6 (converged)
    int hp = lane & 1;
    int bws = (bj * w) / OUT;
    int bwe = ((bj + 1) * w + OUT - 1) / OUT;
    float inv_area = 1.0f / (float)(nrows * (bwe - bws));
    bool writer = (hp == 0) && (lane < 14);
    size_t obase = (((size_t)b * (NROIS * CC)) + (size_t)roi * CC + c0)
                   * (OUT * OUT) + g * OUT + bj;

    // ---- stage plane k's row group into buffer k&1 (warp-private) ----
    auto stage = [&](int k) {
        const char* gp = gbase + (size_t)k * (HH * WW * 4);
        uint32_t    dp = sbw[k & 1];
        for (int r = half; r < nrows; r += 2) {
            if (doA) cp_async16(dp, gp);
            if (doX) cp_async16(dp + 16u, gp + 16);
            gp += 2 * (WW * 4);
            dp += 2u * TS * 4u;
        }
        cp_commit();
    };

    stage(0);
    #pragma unroll
    for (int k = 0; k < KP; ++k) {
        if (k + 1 < KP) { stage(k + 1); cp_wait<1>(); }
        else            { cp_wait<0>(); }
        __syncwarp();

        const float* buf = tile[g][k & 1];

        // vertical, parity-split: lane = chunk(0..15) + 16*rowparity
        {
            float4 a = make_float4(0.f, 0.f, 0.f, 0.f);
            const float4* p = (const float4*)(buf + half * TS) + laneA;
            for (int r = half; r < nrows; r += 2) {
                float4 v = *p;
                a.x += v.x; a.y += v.y; a.z += v.z; a.w += v.w;
                p += 2 * (TS / 4);
            }
            a.x += __shfl_xor_sync(0xffffffffu, a.x, 16);
            a.y += __shfl_xor_sync(0xffffffffu, a.y, 16);
            a.z += __shfl_xor_sync(0xffffffffu, a.z, 16);
            a.w += __shfl_xor_sync(0xffffffffu, a.w, 16);
            if (lane < 16) ((float4*)colsum[g])[lane] = a;

            if (nc > 16) {             // warp-uniform branch, rare
                float4 a2 = make_float4(0.f, 0.f, 0.f, 0.f);
                if (lane < nrows)
                    a2 = *((const float4*)(buf + lane * TS) + 16);
                #pragma unroll
                for (int o = 8; o; o >>= 1) {
                    a2.x += __shfl_xor_sync(0xffffffffu, a2.x, o);
                    a2.y += __shfl_xor_sync(0xffffffffu, a2.y, o);
                    a2.z += __shfl_xor_sync(0xffffffffu, a2.z, o);
                    a2.w += __shfl_xor_sync(0xffffffffu, a2.w, o);
                }
                if (lane == 0) ((float4*)colsum[g])[16] = a2;
            }
        }
        __syncwarp();

        // horizontal, parity-split: 2 lanes per bin, shfl combine
        {
            const float* cs = colsum[g] + ox;
            float s = 0.0f;
            for (int cc = bws + hp; cc < bwe; cc += 2)
                s += cs[cc];
            s += __shfl_xor_sync(0xffffffffu, s, 1);
            if (writer)
                out[obase + (size_t)k * (OUT * OUT)] = s * inv_area;
        }
        __syncwarp();   // colsum[g] reused next plane
    }
}

extern "C" void kernel_launch(void* const* d_in, const int* in_sizes, int n_in,
                              void* d_out, int out_size)
{
    const float* x    = (const float*)d_in[0];
    const void*  rois = d_in[1];
    float*       out  = (float*)d_out;

    roi_adaptive_pool_kernel<<<NROIS * BB * (CC / KP), 224>>>(x, rois, out);
}

// round 17
// speedup vs baseline: 1.0642x; 1.0642x over previous
#include <cuda_runtime.h>
#include <cstddef>
#include <cstdint>

// Problem constants (match reference)
#define BB 4
#define CC 256
#define HH 512
#define WW 512
#define NROIS 32
#define OUT 7
#define TS 68        // row stride in floats (16B-aligned, 17 chunks)
#define KP 8         // planes (channels) per CTA
#define HRW 10       // max rows in one output row-group (h<=63 -> <=10)

__device__ __forceinline__ void cp_async16(uint32_t smem_dst, const void* gmem_src) {
    asm volatile("cp.async.cg.shared.global [%0], [%1], 16;\n"
                 :: "r"(smem_dst), "l"(gmem_src));
}
__device__ __forceinline__ void cp_commit() {
    asm volatile("cp.async.commit_group;\n" ::: "memory");
}
template <int N>
__device__ __forceinline__ void cp_wait() {
    asm volatile("cp.async.wait_group %0;\n" :: "n"(N) : "memory");
}
__device__ __forceinline__ void addf32x2(unsigned long long& acc, unsigned long long v) {
    asm("add.rn.f32x2 %0, %0, %1;" : "+l"(acc) : "l"(v));
}

// One CTA per (roi, b, c-group-of-8), 224 threads = 7 autonomous warps.
// Warp g owns output row-group g end-to-end: stages its own <=10 ROI rows
// into a warp-private double buffer (cp.async, one plane prefetched),
// reduces vertically with packed add.rn.f32x2 (2 packed adds per 16 B),
// then lanes 0..6 finish the 7 bins. No __syncthreads anywhere.
__global__ __launch_bounds__(224)
void roi_adaptive_pool_kernel(const float* __restrict__ x,
                              const void* __restrict__ rois_raw,
                              float* __restrict__ out)
{
    int bid  = blockIdx.x;
    int roi  = bid & (NROIS - 1);     // fastest dim -> balanced waves
    int rest = bid >> 5;
    int cg   = rest & (CC / KP - 1);  // 0..31
    int b    = rest >> 5;

    // ---- inline dtype probe + box read (L2-resident after wave 1) ----
    const long long* r64 = (const long long*)rois_raw;
    const int*       r32 = (const int*)rois_raw;
    long long p0 = r64[0], p1 = r64[1], p2 = r64[2], p3 = r64[3];
    bool is64 = (p0 >= 0 && p0 <= WW) && (p1 >= 0 && p1 <= HH) &&
                (p2 > p0 && p2 <= WW) && (p3 > p1 && p3 <= HH);
    int x1, y1, x2, y2;
    if (is64) {
        const long long* r = r64 + (size_t)roi * 4;
        x1 = (int)r[0]; y1 = (int)r[1]; x2 = (int)r[2]; y2 = (int)r[3];
    } else {
        const int* r = r32 + (size_t)roi * 4;
        x1 = r[0]; y1 = r[1]; x2 = r[2]; y2 = r[3];
    }

    int w  = x2 - x1;                  // 16..63
    int h  = y2 - y1;                  // 16..63
    int xa = x1 & ~3;                  // 16B-aligned row start
    int ox = x1 - xa;                  // 0..3
    int nc = (x2 - xa + 3) >> 2;       // float4 chunks per row (4..17)

    __shared__ float tile[OUT][2][HRW * TS];   // 7 x 2 x 2720 B = 38080 B
    __shared__ float colsum[OUT][TS];          // 1904 B

    int c0 = cg * KP;
    const float* plane0 = x + ((size_t)(b * CC + c0)) * (HH * WW);

    int lane = threadIdx.x & 31;
    int g    = threadIdx.x >> 5;       // warp id = output row group 0..6

    int ghs = (g * h) / OUT;
    int ghe = ((g + 1) * h + OUT - 1) / OUT;   // <= 10 rows
    int nrows = ghe - ghs;

    // staging: laneA = chunk (0..15), half = row parity within group
    int laneA = lane & 15;
    int half  = lane >> 4;
    int ncm   = nc < 16 ? nc : 16;
    bool doA  = laneA < ncm;
    bool doX  = (nc > 16) && (laneA == 15);    // 17th chunk

    const char* gbase = (const char*)(plane0 + (size_t)(y1 + ghs + half) * WW + xa)
                        + laneA * 16;
    uint32_t sbw[2];
    sbw[0] = (uint32_t)__cvta_generic_to_shared(tile[g][0])
             + (uint32_t)(half * TS + laneA * 4) * 4u;
    sbw[1] = (uint32_t)__cvta_generic_to_shared(tile[g][1])
             + (uint32_t)(half * TS + laneA * 4) * 4u;

    // horizontal geometry for lanes 0..6 (bin (g, lane))
    int bws = 0, bwe = 0;
    float inv_area = 0.f;
    if (lane < OUT) {
        bws = (lane * w) / OUT;
        bwe = ((lane + 1) * w + OUT - 1) / OUT;
        inv_area = 1.0f / (float)(nrows * (bwe - bws));
    }
    size_t obase = (((size_t)b * (NROIS * CC)) + (size_t)roi * CC + c0)
                   * (OUT * OUT) + g * OUT + lane;

    // ---- stage plane k's row group into buffer k&1 (warp-private) ----
    auto stage = [&](int k) {
        const char* gp = gbase + (size_t)k * (HH * WW * 4);
        uint32_t    dp = sbw[k & 1];
        for (int r = half; r < nrows; r += 2) {
            if (doA) cp_async16(dp, gp);
            if (doX) cp_async16(dp + 16u, gp + 16);
            gp += 2 * (WW * 4);
            dp += 2u * TS * 4u;
        }
        cp_commit();
    };

    stage(0);
    #pragma unroll
    for (int k = 0; k < KP; ++k) {
        if (k + 1 < KP) { stage(k + 1); cp_wait<1>(); }
        else            { cp_wait<0>(); }
        __syncwarp();

        // vertical: lane = chunk; packed f32x2 column sums over nrows
        if (lane < nc) {
            unsigned long long a01 = 0ull, a23 = 0ull;   // packed {0.f,0.f}
            const ulonglong2* p = (const ulonglong2*)tile[g][k & 1] + lane;
            #pragma unroll 4
            for (int r = 0; r < nrows; ++r) {
                ulonglong2 v = *p;
                addf32x2(a01, v.x);
                addf32x2(a23, v.y);
                p += TS / 4;
            }
            ((ulonglong2*)colsum[g])[lane] = make_ulonglong2(a01, a23);
        }
        __syncwarp();

        // horizontal: lanes 0..6 each finish one bin
        if (lane < OUT) {
            const float* cs = colsum[g] + ox + bws;
            int ncol = bwe - bws;
            float s = 0.0f;
            #pragma unroll 4
            for (int cc = 0; cc < ncol; ++cc)
                s += cs[cc];
            out[obase + (size_t)k * (OUT * OUT)] = s * inv_area;
        }
        __syncwarp();   // colsum[g] reused next plane
    }
}

extern "C" void kernel_launch(void* const* d_in, const int* in_sizes, int n_in,
                              void* d_out, int out_size)
{
    const float* x    = (const float*)d_in[0];
    const void*  rois = d_in[1];
    float*       out  = (float*)d_out;

    roi_adaptive_pool_kernel<<<NROIS * BB * (CC / KP), 224>>>(x, rois, out);
}